// round 2
// baseline (speedup 1.0000x reference)
#include <cuda_runtime.h>
#include <cuda_bf16.h>
#include <cstdint>

// SynergyGraph: out[b,s,t] = (W[seq[b,s]] . W[seq[b,t]]) / sqrt(64)
// B=16, S=2048, D=64, VOCAB=32000. Output fp32 [16,2048,2048].
//
// sm_103 (no 'a' feature in harness PTX target) -> no tcgen05. Use classic
// ldmatrix + mma.sync m16n8k16 bf16 with fp32 accumulators.
// Accuracy: split fp32 -> bf16 hi + bf16 lo, accumulate hi*hi + hi*lo + lo*hi
// (3 passes into the same fp32 register accumulators) -> ~1e-5 rel err.

#define DEVFN __device__ __forceinline__

static constexpr int BATCH = 16;
static constexpr int SEQ   = 2048;
static constexpr int DIMK  = 64;
static constexpr int TILE  = 128;
static constexpr int NT    = SEQ / TILE;   // 16

// SMEM: 4 tiles (Ahi, Alo, Bhi, Blo), each 128 rows x 72 bf16 (padded from 64
// to kill bank conflicts; 144B row stride keeps 16B alignment for ldmatrix).
static constexpr int LDE        = 72;                // elements per padded row
static constexpr int ROW_BYTES  = LDE * 2;           // 144
static constexpr int TILE_BYTES = TILE * ROW_BYTES;  // 18432
static constexpr int OFF_AHI = 0;
static constexpr int OFF_ALO = TILE_BYTES;
static constexpr int OFF_BHI = 2 * TILE_BYTES;
static constexpr int OFF_BLO = 3 * TILE_BYTES;
static constexpr int SMEM_BYTES = 4 * TILE_BYTES;    // 73728

DEVFN uint32_t smem_u32(const void* p) {
    uint32_t a;
    asm("{ .reg .u64 t; cvta.to.shared.u64 t, %1; cvt.u32.u64 %0, t; }"
        : "=r"(a) : "l"(p));
    return a;
}

DEVFN void sts128(uint32_t addr, uint32_t a, uint32_t b, uint32_t c, uint32_t d) {
    asm volatile("st.shared.v4.b32 [%0], {%1, %2, %3, %4};"
                 :: "r"(addr), "r"(a), "r"(b), "r"(c), "r"(d) : "memory");
}

DEVFN void ldsm4(uint32_t* r, uint32_t addr) {
    asm volatile("ldmatrix.sync.aligned.m8n8.x4.shared.b16 {%0, %1, %2, %3}, [%4];"
                 : "=r"(r[0]), "=r"(r[1]), "=r"(r[2]), "=r"(r[3]) : "r"(addr));
}

DEVFN void mma16816(float* c, const uint32_t* a, uint32_t b0, uint32_t b1) {
    asm volatile(
        "mma.sync.aligned.m16n8k16.row.col.f32.bf16.bf16.f32 "
        "{%0, %1, %2, %3}, {%4, %5, %6, %7}, {%8, %9}, {%0, %1, %2, %3};"
        : "+f"(c[0]), "+f"(c[1]), "+f"(c[2]), "+f"(c[3])
        : "r"(a[0]), "r"(a[1]), "r"(a[2]), "r"(a[3]), "r"(b0), "r"(b1));
}

// split two fp32 into packed bf16x2 hi + bf16x2 lo words
DEVFN void split2(float f0, float f1, uint32_t& hi, uint32_t& lo) {
    __nv_bfloat16 h0 = __float2bfloat16_rn(f0);
    __nv_bfloat16 h1 = __float2bfloat16_rn(f1);
    float r0 = f0 - __bfloat162float(h0);
    float r1 = f1 - __bfloat162float(h1);
    __nv_bfloat16 l0 = __float2bfloat16_rn(r0);
    __nv_bfloat16 l1 = __float2bfloat16_rn(r1);
    hi = (uint32_t)__bfloat16_as_ushort(h0) | ((uint32_t)__bfloat16_as_ushort(h1) << 16);
    lo = (uint32_t)__bfloat16_as_ushort(l0) | ((uint32_t)__bfloat16_as_ushort(l1) << 16);
}

__global__ void __launch_bounds__(256, 2)
synergy_kernel(const int* __restrict__ seq,
               const float* __restrict__ weight,
               float* __restrict__ out)
{
    extern __shared__ char smem_raw[];
    const uint32_t smem = smem_u32(smem_raw);

    const int tid  = threadIdx.x;
    const int wid  = tid >> 5;
    const int lane = tid & 31;

    const int nT = blockIdx.x;
    const int mT = blockIdx.y;
    const int bb = blockIdx.z;

    // ---- Gather + split: thread r handles one embedding row (A: 0..127, B: 128..255)
    {
        const int r    = tid;
        const bool isA = (r < 128);
        const int row  = r & 127;
        const int pos  = (isA ? mT : nT) * TILE + row;
        const int idx  = seq[bb * SEQ + pos];
        const float4* w = reinterpret_cast<const float4*>(weight) + (size_t)idx * (DIMK / 4);

        const uint32_t hbase = smem + (isA ? OFF_AHI : OFF_BHI) + row * ROW_BYTES;
        const uint32_t lbase = hbase + TILE_BYTES;  // ALO/BLO follow AHI/BHI

        #pragma unroll
        for (int i = 0; i < 8; ++i) {
            float4 x = w[2 * i], y = w[2 * i + 1];
            uint32_t h0, l0, h1, l1, h2, l2, h3, l3;
            split2(x.x, x.y, h0, l0);
            split2(x.z, x.w, h1, l1);
            split2(y.x, y.y, h2, l2);
            split2(y.z, y.w, h3, l3);
            sts128(hbase + i * 16, h0, h1, h2, h3);
            sts128(lbase + i * 16, l0, l1, l2, l3);
        }
    }
    __syncthreads();

    // ---- Warp tiling: 8 warps = 2 (M) x 4 (N); warp tile 64x32
    const int wm = (wid >> 2) * 64;   // 0 or 64
    const int wn = (wid & 3) * 32;    // 0,32,64,96

    float acc[4][4][4];
    #pragma unroll
    for (int mi = 0; mi < 4; ++mi)
        #pragma unroll
        for (int nj = 0; nj < 4; ++nj)
            #pragma unroll
            for (int q = 0; q < 4; ++q) acc[mi][nj][q] = 0.f;

    // ldmatrix lane address components
    const int a_row  = lane & 15;          // rows of m16 tile
    const int a_col  = (lane >> 4) * 8;    // k halves
    const int b_row  = (lane & 7) + ((lane >> 4) * 8); // n within n16 pair
    const int b_col  = ((lane >> 3) & 1) * 8;          // k halves

    #pragma unroll
    for (int pass = 0; pass < 3; ++pass) {
        // pass 0: Ahi*Bhi, pass 1: Ahi*Blo, pass 2: Alo*Bhi
        const uint32_t abase = smem + (pass == 2 ? OFF_ALO : OFF_AHI);
        const uint32_t bbase = smem + (pass == 1 ? OFF_BLO : OFF_BHI);

        #pragma unroll
        for (int k = 0; k < 4; ++k) {           // k16 steps over K=64
            const uint32_t a_off =
                abase + (uint32_t)(wm + a_row) * ROW_BYTES + (uint32_t)(k * 16 + a_col) * 2;
            const uint32_t b_off =
                bbase + (uint32_t)(wn + b_row) * ROW_BYTES + (uint32_t)(k * 16 + b_col) * 2;

            uint32_t af[4][4];
            #pragma unroll
            for (int mi = 0; mi < 4; ++mi)
                ldsm4(af[mi], a_off + (uint32_t)(mi * 16) * ROW_BYTES);

            uint32_t bf2[2][4];
            #pragma unroll
            for (int bj = 0; bj < 2; ++bj)
                ldsm4(bf2[bj], b_off + (uint32_t)(bj * 16) * ROW_BYTES);

            #pragma unroll
            for (int mi = 0; mi < 4; ++mi) {
                #pragma unroll
                for (int nj = 0; nj < 4; ++nj) {
                    const uint32_t* bp = &bf2[nj >> 1][(nj & 1) * 2];
                    mma16816(acc[mi][nj], af[mi], bp[0], bp[1]);
                }
            }
        }
    }

    // ---- Epilogue: scale by 1/sqrt(64) = 0.125, store float2 per frag-row
    const int g = lane >> 2;    // row within 8
    const int t = lane & 3;     // col pair
    float* obase = out + ((size_t)bb * SEQ + (size_t)(mT * TILE + wm + g)) * SEQ
                       + (size_t)(nT * TILE + wn + 2 * t);

    #pragma unroll
    for (int mi = 0; mi < 4; ++mi) {
        #pragma unroll
        for (int h = 0; h < 2; ++h) {
            float* rowp = obase + (size_t)(mi * 16 + 8 * h) * SEQ;
            #pragma unroll
            for (int nj = 0; nj < 4; ++nj) {
                float2 v;
                v.x = acc[mi][nj][2 * h + 0] * 0.125f;
                v.y = acc[mi][nj][2 * h + 1] * 0.125f;
                *reinterpret_cast<float2*>(rowp + nj * 8) = v;
            }
        }
    }
}

extern "C" void kernel_launch(void* const* d_in, const int* in_sizes, int n_in,
                              void* d_out, int out_size)
{
    const int*   seq    = (const int*)d_in[0];    // [16, 2048] int32
    const float* weight = (const float*)d_in[1];  // [32000, 64] fp32
    float*       out    = (float*)d_out;          // [16, 2048, 2048] fp32

    (void)in_sizes; (void)n_in; (void)out_size;

    cudaFuncSetAttribute(synergy_kernel,
                         cudaFuncAttributeMaxDynamicSharedMemorySize, SMEM_BYTES);

    dim3 grid(NT, NT, BATCH);   // (16, 16, 16)
    synergy_kernel<<<grid, 256, SMEM_BYTES>>>(seq, weight, out);
}